// round 3
// baseline (speedup 1.0000x reference)
#include <cuda_runtime.h>
#include <stdint.h>

#define H      128
#define OUTD   64
#define NC_MAX 100000
#define NU_MAX 100000
#define E_MAX  1600000

// Scratch: __device__ globals (allocation-free rule)
__device__ __align__(16) float g_hu[(size_t)NU_MAX * H];
__device__ __align__(16) float g_hc[(size_t)NC_MAX * H];
__device__ __align__(16) float g_mean[(size_t)NC_MAX * H];
__device__ int g_deg[NC_MAX];
__device__ int g_off[NC_MAX];
__device__ int g_cursor[NC_MAX];
__device__ int g_csr[E_MAX];
__device__ int g_bsum[512];

// ---------------------------------------------------------------------------
__global__ void zero_deg_kernel(int nc) {
    int i = blockIdx.x * blockDim.x + threadIdx.x;
    int stride = gridDim.x * blockDim.x;
    for (; i < nc; i += stride) g_deg[i] = 0;
}

// NOTE: edge_index is int32 on device (JAX downcasts int64 without x64 mode)
__global__ void hist_kernel(const int* __restrict__ ei, int E) {
    int i = blockIdx.x * blockDim.x + threadIdx.x;
    if (i < E) atomicAdd(&g_deg[ei[E + i]], 1);
}

// Block-wise scan (3 passes). NB <= 512 blocks of 256.
__global__ void scan1_kernel(int nc) {
    __shared__ int s[256];
    int t = threadIdx.x;
    int i = blockIdx.x * 256 + t;
    s[t] = (i < nc) ? g_deg[i] : 0;
    __syncthreads();
    for (int d = 128; d > 0; d >>= 1) {
        if (t < d) s[t] += s[t + d];
        __syncthreads();
    }
    if (t == 0) g_bsum[blockIdx.x] = s[0];
}

__global__ void scan2_kernel(int nb) {
    __shared__ int s[512];
    int t = threadIdx.x;
    int v = (t < nb) ? g_bsum[t] : 0;
    s[t] = v;
    __syncthreads();
    for (int d = 1; d < 512; d <<= 1) {
        int add = (t >= d) ? s[t - d] : 0;
        __syncthreads();
        s[t] += add;
        __syncthreads();
    }
    if (t < nb) g_bsum[t] = s[t] - v;  // exclusive block offsets
}

__global__ void scan3_kernel(int nc) {
    __shared__ int s[256];
    int t = threadIdx.x;
    int i = blockIdx.x * 256 + t;
    int v = (i < nc) ? g_deg[i] : 0;
    s[t] = v;
    __syncthreads();
    for (int d = 1; d < 256; d <<= 1) {
        int add = (t >= d) ? s[t - d] : 0;
        __syncthreads();
        s[t] += add;
        __syncthreads();
    }
    if (i < nc) {
        int off = g_bsum[blockIdx.x] + s[t] - v;  // exclusive
        g_off[i] = off;
        g_cursor[i] = off;
    }
}

__global__ void fill_kernel(const int* __restrict__ ei, int E) {
    int i = blockIdx.x * blockDim.x + threadIdx.x;
    if (i < E) {
        int dst = ei[E + i];
        int pos = atomicAdd(&g_cursor[dst], 1);
        g_csr[pos] = ei[i];
    }
}

// ---------------------------------------------------------------------------
// Projection: h = relu(x @ W + b), x:[N,K], W:[K,128].
// Block tile 64 rows x 128 cols, 256 threads, 8x4 register tile per thread.
// WHICH: 0 -> g_hu, 1 -> g_hc.
// ---------------------------------------------------------------------------
template <int K, int WHICH>
__global__ void proj_kernel(const float* __restrict__ x,
                            const float* __restrict__ W,
                            const float* __restrict__ b, int N) {
    extern __shared__ float sm[];
    float* Ws = sm;             // K*128
    float* xs = sm + K * H;     // 64*K (row-major)
    float* hout = (WHICH == 0) ? g_hu : g_hc;

    const int t = threadIdx.x;
    {
        const float4* W4 = reinterpret_cast<const float4*>(W);
        float4* Ws4 = reinterpret_cast<float4*>(Ws);
        for (int i = t; i < K * H / 4; i += 256) Ws4[i] = W4[i];
    }
    const int tx = t & 31;           // col group: cols tx*4 .. tx*4+3
    const int ty = t >> 5;           // row group: rows ty*8 .. ty*8+7
    const int col0 = tx * 4;
    const int row_off = ty * 8;
    const float4 b4 = reinterpret_cast<const float4*>(b)[tx];

    const int ntiles = (N + 63) >> 6;
    for (int tile = blockIdx.x; tile < ntiles; tile += gridDim.x) {
        const int row0 = tile << 6;
        __syncthreads();  // Ws first iter / xs reuse
        {
            float4* xs4 = reinterpret_cast<float4*>(xs);
            const int nf4 = 64 * (K / 4);
            for (int i = t; i < nf4; i += 256) {
                int r = i / (K / 4);
                int c4 = i % (K / 4);
                int rr = row0 + r;
                xs4[i] = (rr < N)
                             ? reinterpret_cast<const float4*>(x + (size_t)rr * K)[c4]
                             : make_float4(0.f, 0.f, 0.f, 0.f);
            }
        }
        __syncthreads();

        float acc[8][4];
#pragma unroll
        for (int r = 0; r < 8; r++)
#pragma unroll
            for (int c = 0; c < 4; c++) acc[r][c] = 0.f;

        const float* xb = xs + row_off * K;
#pragma unroll 4
        for (int k = 0; k < K; k++) {
            float4 w = reinterpret_cast<const float4*>(Ws + k * H)[tx];
            float a[8];
#pragma unroll
            for (int r = 0; r < 8; r++) a[r] = xb[r * K + k];
#pragma unroll
            for (int r = 0; r < 8; r++) {
                acc[r][0] += a[r] * w.x;
                acc[r][1] += a[r] * w.y;
                acc[r][2] += a[r] * w.z;
                acc[r][3] += a[r] * w.w;
            }
        }
#pragma unroll
        for (int r = 0; r < 8; r++) {
            int rr = row0 + row_off + r;
            if (rr < N) {
                float4 o;
                o.x = fmaxf(acc[r][0] + b4.x, 0.f);
                o.y = fmaxf(acc[r][1] + b4.y, 0.f);
                o.z = fmaxf(acc[r][2] + b4.z, 0.f);
                o.w = fmaxf(acc[r][3] + b4.w, 0.f);
                reinterpret_cast<float4*>(hout + (size_t)rr * H + col0)[0] = o;
            }
        }
    }
}

// ---------------------------------------------------------------------------
// Gather-mean: warp per content node. Lanes each own a float4 slice (512B/row).
// ---------------------------------------------------------------------------
__global__ void agg_kernel(int nc) {
    const int warp = (blockIdx.x * blockDim.x + threadIdx.x) >> 5;
    const int lane = threadIdx.x & 31;
    if (warp >= nc) return;
    const int s0 = g_off[warp];
    const int d = g_deg[warp];
    float4 acc = make_float4(0.f, 0.f, 0.f, 0.f);
    for (int base = 0; base < d; base += 32) {
        int my = (base + lane < d) ? g_csr[s0 + base + lane] : 0;
        int lim = min(32, d - base);
        for (int j = 0; j < lim; j++) {
            int nbr = __shfl_sync(0xffffffffu, my, j);
            float4 v = reinterpret_cast<const float4*>(g_hu + (size_t)nbr * H)[lane];
            acc.x += v.x; acc.y += v.y; acc.z += v.z; acc.w += v.w;
        }
    }
    float inv = 1.f / fmaxf((float)d, 1.f);
    acc.x *= inv; acc.y *= inv; acc.z *= inv; acc.w *= inv;
    reinterpret_cast<float4*>(g_mean + (size_t)warp * H)[lane] = acc;
}

// ---------------------------------------------------------------------------
// Fused combine: h = mean @ Wl + bl + h_c @ Wr (in smem); out = h @ Wo + bo.
// Block tile 64 rows. Wl/Wr/Wo smem-resident (224KB total).
// ---------------------------------------------------------------------------
__global__ void combine_kernel(const float* __restrict__ Wl,
                               const float* __restrict__ bl,
                               const float* __restrict__ Wr,
                               const float* __restrict__ Wo,
                               const float* __restrict__ bo,
                               float* __restrict__ out, int N) {
    extern __shared__ float sm[];
    float* Wl_s = sm;                    // 128*128
    float* Wr_s = Wl_s + H * H;          // 128*128
    float* Wo_s = Wr_s + H * H;          // 128*64
    float* ms = Wo_s + H * OUTD;         // 64*128 (mean tile, reused as h tile)
    float* cs = ms + 64 * H;             // 64*128 (h_c tile)

    const int t = threadIdx.x;
    {
        const float4* a4 = reinterpret_cast<const float4*>(Wl);
        const float4* b4 = reinterpret_cast<const float4*>(Wr);
        float4* as4 = reinterpret_cast<float4*>(Wl_s);
        float4* bs4 = reinterpret_cast<float4*>(Wr_s);
        for (int i = t; i < H * H / 4; i += 256) {
            as4[i] = a4[i];
            bs4[i] = b4[i];
        }
        const float4* o4 = reinterpret_cast<const float4*>(Wo);
        float4* os4 = reinterpret_cast<float4*>(Wo_s);
        for (int i = t; i < H * OUTD / 4; i += 256) os4[i] = o4[i];
    }

    const int tx = t & 31;
    const int ty = t >> 5;
    const int col0 = tx * 4;
    const int row_off = ty * 8;
    const float4 bl4 = reinterpret_cast<const float4*>(bl)[tx];
    const float2 bo2 = reinterpret_cast<const float2*>(bo)[tx];

    const int ntiles = (N + 63) >> 6;
    for (int tile = blockIdx.x; tile < ntiles; tile += gridDim.x) {
        const int row0 = tile << 6;
        __syncthreads();
        {
            float4* ms4 = reinterpret_cast<float4*>(ms);
            float4* cs4 = reinterpret_cast<float4*>(cs);
            for (int i = t; i < 64 * (H / 4); i += 256) {
                int r = i / (H / 4);
                int c4 = i % (H / 4);
                int rr = row0 + r;
                if (rr < N) {
                    ms4[i] = reinterpret_cast<const float4*>(g_mean + (size_t)rr * H)[c4];
                    cs4[i] = reinterpret_cast<const float4*>(g_hc + (size_t)rr * H)[c4];
                } else {
                    ms4[i] = make_float4(0.f, 0.f, 0.f, 0.f);
                    cs4[i] = make_float4(0.f, 0.f, 0.f, 0.f);
                }
            }
        }
        __syncthreads();

        // GEMM1: h = ms @ Wl + cs @ Wr + bl
        float acc[8][4];
#pragma unroll
        for (int r = 0; r < 8; r++)
#pragma unroll
            for (int c = 0; c < 4; c++) acc[r][c] = 0.f;
        const float* mb = ms + row_off * H;
        const float* cb = cs + row_off * H;
#pragma unroll 2
        for (int k = 0; k < H; k++) {
            float4 wl = reinterpret_cast<const float4*>(Wl_s + k * H)[tx];
            float4 wr = reinterpret_cast<const float4*>(Wr_s + k * H)[tx];
            float am[8], ac[8];
#pragma unroll
            for (int r = 0; r < 8; r++) {
                am[r] = mb[r * H + k];
                ac[r] = cb[r * H + k];
            }
#pragma unroll
            for (int r = 0; r < 8; r++) {
                acc[r][0] += am[r] * wl.x + ac[r] * wr.x;
                acc[r][1] += am[r] * wl.y + ac[r] * wr.y;
                acc[r][2] += am[r] * wl.z + ac[r] * wr.z;
                acc[r][3] += am[r] * wl.w + ac[r] * wr.w;
            }
        }
        __syncthreads();  // all reads of ms done before overwrite with h
#pragma unroll
        for (int r = 0; r < 8; r++) {
            float4 hv;
            hv.x = acc[r][0] + bl4.x;
            hv.y = acc[r][1] + bl4.y;
            hv.z = acc[r][2] + bl4.z;
            hv.w = acc[r][3] + bl4.w;
            reinterpret_cast<float4*>(ms + (row_off + r) * H + col0)[0] = hv;
        }
        __syncthreads();

        // GEMM2: out = h @ Wo + bo  (64 x 64), thread: rows row_off..+7, cols tx*2..+1
        float acc2[8][2];
#pragma unroll
        for (int r = 0; r < 8; r++) { acc2[r][0] = 0.f; acc2[r][1] = 0.f; }
        const float* hb = ms + row_off * H;
#pragma unroll 2
        for (int k = 0; k < H; k++) {
            float2 wo = reinterpret_cast<const float2*>(Wo_s + k * OUTD)[tx];
#pragma unroll
            for (int r = 0; r < 8; r++) {
                float a = hb[r * H + k];
                acc2[r][0] += a * wo.x;
                acc2[r][1] += a * wo.y;
            }
        }
#pragma unroll
        for (int r = 0; r < 8; r++) {
            int rr = row0 + row_off + r;
            if (rr < N) {
                float2 o;
                o.x = acc2[r][0] + bo2.x;
                o.y = acc2[r][1] + bo2.y;
                reinterpret_cast<float2*>(out + (size_t)rr * OUTD + tx * 2)[0] = o;
            }
        }
    }
}

// ---------------------------------------------------------------------------
extern "C" void kernel_launch(void* const* d_in, const int* in_sizes, int n_in,
                              void* d_out, int out_size) {
    const float* x_content = (const float*)d_in[0];
    const float* x_user    = (const float*)d_in[1];
    const int*   ei        = (const int*)d_in[2];   // int32! (JAX x64 off)
    const float* Wc = (const float*)d_in[3];
    const float* bc = (const float*)d_in[4];
    const float* Wu = (const float*)d_in[5];
    const float* bu = (const float*)d_in[6];
    const float* Wl = (const float*)d_in[7];
    const float* bl = (const float*)d_in[8];
    const float* Wr = (const float*)d_in[9];
    const float* Wo = (const float*)d_in[10];
    const float* bo = (const float*)d_in[11];
    float* out = (float*)d_out;

    const int Nc = in_sizes[0] / 256;
    const int Nu = in_sizes[1] / 128;
    const int E  = in_sizes[2] / 2;

    const int smem_proj_c = (256 * H + 64 * 256) * sizeof(float);  // 192KB
    const int smem_proj_u = (128 * H + 64 * 128) * sizeof(float);  // 96KB
    const int smem_combine =
        (2 * H * H + H * OUTD + 2 * 64 * H) * sizeof(float);        // 224KB

    cudaFuncSetAttribute(proj_kernel<256, 1>,
                         cudaFuncAttributeMaxDynamicSharedMemorySize, smem_proj_c);
    cudaFuncSetAttribute(proj_kernel<128, 0>,
                         cudaFuncAttributeMaxDynamicSharedMemorySize, smem_proj_u);
    cudaFuncSetAttribute(combine_kernel,
                         cudaFuncAttributeMaxDynamicSharedMemorySize, smem_combine);

    // CSR build
    zero_deg_kernel<<<256, 256>>>(Nc);
    hist_kernel<<<(E + 255) / 256, 256>>>(ei, E);
    const int nb = (Nc + 255) / 256;  // <= 512
    scan1_kernel<<<nb, 256>>>(Nc);
    scan2_kernel<<<1, 512>>>(nb);
    scan3_kernel<<<nb, 256>>>(Nc);
    fill_kernel<<<(E + 255) / 256, 256>>>(ei, E);

    // Projections
    proj_kernel<128, 0><<<304, 256, smem_proj_u>>>(x_user, Wu, bu, Nu);
    proj_kernel<256, 1><<<152, 256, smem_proj_c>>>(x_content, Wc, bc, Nc);

    // Gather-mean (needs g_hu; stream order guarantees)
    agg_kernel<<<(Nc * 32 + 255) / 256, 256>>>(Nc);

    // Fused combine + output projection
    combine_kernel<<<152, 256, smem_combine>>>(Wl, bl, Wr, Wo, bo, out, Nc);
}

// round 6
// speedup vs baseline: 1.6160x; 1.6160x over previous
#include <cuda_runtime.h>
#include <cuda_bf16.h>
#include <stdint.h>

#define H      128
#define OUTD   64
#define NC_MAX 100000
#define NU_MAX 100000
#define E_MAX  1600000

// Scratch: __device__ globals (allocation-free rule)
__device__ __align__(16) float g_hu[(size_t)NU_MAX * H];
__device__ __align__(16) float g_hc[(size_t)NC_MAX * H];
__device__ __align__(16) float g_mean[(size_t)NC_MAX * H];
__device__ __align__(16) float g_h[(size_t)NC_MAX * H];
__device__ int g_deg[NC_MAX];
__device__ int g_off[NC_MAX];
__device__ int g_cursor[NC_MAX];
__device__ int g_csr[E_MAX];
__device__ int g_bsum[512];

// ============================= PTX helpers (portable) =======================
__device__ __forceinline__ uint32_t smem_u32(const void* p) {
    uint32_t a;
    asm("{ .reg .u64 t; cvta.to.shared.u64 t, %1; cvt.u32.u64 %0, t; }"
        : "=r"(a) : "l"(p));
    return a;
}
__device__ __forceinline__ void ldsm_x4(uint32_t* r, uint32_t addr) {
    asm volatile("ldmatrix.sync.aligned.m8n8.x4.shared.b16 {%0,%1,%2,%3}, [%4];"
                 : "=r"(r[0]), "=r"(r[1]), "=r"(r[2]), "=r"(r[3]) : "r"(addr));
}
__device__ __forceinline__ void ldsm_x4_t(uint32_t* r, uint32_t addr) {
    asm volatile("ldmatrix.sync.aligned.m8n8.x4.trans.shared.b16 {%0,%1,%2,%3}, [%4];"
                 : "=r"(r[0]), "=r"(r[1]), "=r"(r[2]), "=r"(r[3]) : "r"(addr));
}
__device__ __forceinline__ void mma_bf16(float* d, const uint32_t* a,
                                         uint32_t b0, uint32_t b1) {
    asm volatile(
        "mma.sync.aligned.m16n8k16.row.col.f32.bf16.bf16.f32 "
        "{%0,%1,%2,%3}, {%4,%5,%6,%7}, {%8,%9}, {%0,%1,%2,%3};"
        : "+f"(d[0]), "+f"(d[1]), "+f"(d[2]), "+f"(d[3])
        : "r"(a[0]), "r"(a[1]), "r"(a[2]), "r"(a[3]), "r"(b0), "r"(b1));
}

// fp32 -> (bf16 hi, bf16 lo) for 4 values, packed
__device__ __forceinline__ void cvt_hl4(float4 v, uint2& hv, uint2& lv) {
    float f[4] = {v.x, v.y, v.z, v.w};
    uint32_t h[4], l[4];
#pragma unroll
    for (int j = 0; j < 4; j++) {
        __nv_bfloat16 hb = __float2bfloat16_rn(f[j]);
        float hf = __bfloat162float(hb);
        __nv_bfloat16 lb = __float2bfloat16_rn(f[j] - hf);
        h[j] = (uint32_t)__bfloat16_as_ushort(hb);
        l[j] = (uint32_t)__bfloat16_as_ushort(lb);
    }
    hv = make_uint2(h[0] | (h[1] << 16), h[2] | (h[3] << 16));
    lv = make_uint2(l[0] | (l[1] << 16), l[2] | (l[3] << 16));
}

// ============================================================================
// HMMA GEMM, bf16 hi/lo 3-pass split, fp32 register accumulators.
// D[row, n] = sum_k A[row,k] * W[k,n] (+bias, opt relu)
// MODE 0: A=x_user(K=128), W=Wu, +relu -> g_hu
// MODE 1: A=x_content(K=256), W=Wc, +relu -> g_hc
// MODE 2: A=[g_mean|g_hc](K=256), W=[Wl;Wr], bias=bl -> g_h
// MODE 3: A=g_h(K=128), W=Wo(NOUT=64), bias=bo -> out
// CTA tile: 128 rows x NOUT cols. 8 warps as 4x2. Warp tile 32 x NOUT/2.
// ============================================================================
template <int KTOT, int NOUT, int MODE>
__global__ void __launch_bounds__(256, 1)
gemm_kernel(const float* __restrict__ X, const float* __restrict__ W0,
            const float* __restrict__ W1, const float* __restrict__ bias,
            float* __restrict__ outp, int N) {
    constexpr int NCHUNK = KTOT / 128;
    constexpr int APITCH = 136;          // bf16 elems/row (272B, 16 mod 128 -> no conflicts)
    constexpr int BPITCH = NOUT + 8;     // 272B or 144B rows
    constexpr int NW = NOUT / 16;        // n8 tiles per warp (8 or 4)

    extern __shared__ char smc[];
    __nv_bfloat16* Ah = reinterpret_cast<__nv_bfloat16*>(smc);
    __nv_bfloat16* Al = Ah + 128 * APITCH;
    __nv_bfloat16* Bh = Al + 128 * APITCH;
    __nv_bfloat16* Bl = Bh + KTOT * BPITCH;

    const int t = threadIdx.x;
    const int wid = t >> 5, lane = t & 31;
    const int wm = wid >> 1, wn = wid & 1;

    // ---- Convert weights once per CTA: B[k][n] (hi/lo bf16) ----
    for (int i = t; i < KTOT * (NOUT / 4); i += 256) {
        int k = i / (NOUT / 4);
        int n4 = (i % (NOUT / 4)) * 4;
        const float* wsrc =
            (MODE == 2) ? ((k < 128) ? W0 + (size_t)k * NOUT
                                     : W1 + (size_t)(k - 128) * NOUT)
                        : W0 + (size_t)k * NOUT;
        float4 w = *reinterpret_cast<const float4*>(wsrc + n4);
        uint2 hv, lv;
        cvt_hl4(w, hv, lv);
        *reinterpret_cast<uint2*>(Bh + k * BPITCH + n4) = hv;
        *reinterpret_cast<uint2*>(Bl + k * BPITCH + n4) = lv;
    }

    const uint32_t ah_u = smem_u32(Ah), al_u = smem_u32(Al);
    const uint32_t bh_u = smem_u32(Bh), bl_u = smem_u32(Bl);

    // lane addressing for ldmatrix
    const int a_row_l = lane & 15;           // row within 16-row tile
    const int a_col_l = (lane >> 4) * 8;     // 0 or 8 within k16
    const int b_k_l = (lane & 7) + ((lane >> 3) & 1) * 8;  // k within k16
    const int b_n_l = (lane >> 4) * 8;       // 0 or 8 within n16 group

    float* dstp = (MODE == 0) ? g_hu : (MODE == 1) ? g_hc : (MODE == 2) ? g_h : outp;

    const int ntiles = (N + 127) >> 7;
    for (int tile = blockIdx.x; tile < ntiles; tile += gridDim.x) {
        const int row0 = tile << 7;
        float acc[2][NW][4];
#pragma unroll
        for (int mt = 0; mt < 2; mt++)
#pragma unroll
            for (int n8 = 0; n8 < NW; n8++)
#pragma unroll
                for (int e = 0; e < 4; e++) acc[mt][n8][e] = 0.f;

        for (int c = 0; c < NCHUNK; ++c) {
            __syncthreads();  // previous chunk's reads done (or weights staged)
            // ---- Convert A chunk: 128 rows x 128 cols ----
            for (int i = t; i < 4096; i += 256) {
                int r = i >> 5;
                int c4 = (i & 31) * 4;
                int rr = row0 + r;
                float4 v = make_float4(0.f, 0.f, 0.f, 0.f);
                if (rr < N) {
                    if (MODE == 2) {
                        const float* src = (c == 0) ? g_mean : g_hc;
                        v = *reinterpret_cast<const float4*>(src + (size_t)rr * 128 + c4);
                    } else if (MODE == 3) {
                        v = *reinterpret_cast<const float4*>(g_h + (size_t)rr * 128 + c4);
                    } else {
                        v = *reinterpret_cast<const float4*>(X + (size_t)rr * KTOT +
                                                             c * 128 + c4);
                    }
                }
                uint2 hv, lv;
                cvt_hl4(v, hv, lv);
                *reinterpret_cast<uint2*>(Ah + r * APITCH + c4) = hv;
                *reinterpret_cast<uint2*>(Al + r * APITCH + c4) = lv;
            }
            __syncthreads();

            // ---- MMA over this 128-wide K chunk ----
#pragma unroll 1
            for (int k0 = 0; k0 < 128; k0 += 16) {
                uint32_t afh[2][4], afl[2][4];
#pragma unroll
                for (int mt = 0; mt < 2; mt++) {
                    uint32_t off =
                        (uint32_t)((wm * 32 + mt * 16 + a_row_l) * APITCH +
                                   k0 + a_col_l) * 2;
                    ldsm_x4(afh[mt], ah_u + off);
                    ldsm_x4(afl[mt], al_u + off);
                }
                uint32_t bfh[NW / 2][4], bfl[NW / 2][4];
#pragma unroll
                for (int ng = 0; ng < NW / 2; ng++) {
                    uint32_t off =
                        (uint32_t)((c * 128 + k0 + b_k_l) * BPITCH +
                                   wn * (NOUT / 2) + ng * 16 + b_n_l) * 2;
                    ldsm_x4_t(bfh[ng], bh_u + off);
                    ldsm_x4_t(bfl[ng], bl_u + off);
                }
#pragma unroll
                for (int mt = 0; mt < 2; mt++) {
#pragma unroll
                    for (int n8 = 0; n8 < NW; n8++) {
                        int ng = n8 >> 1, sb = (n8 & 1) * 2;
                        mma_bf16(acc[mt][n8], afh[mt], bfh[ng][sb], bfh[ng][sb + 1]);
                        mma_bf16(acc[mt][n8], afh[mt], bfl[ng][sb], bfl[ng][sb + 1]);
                        mma_bf16(acc[mt][n8], afl[mt], bfh[ng][sb], bfh[ng][sb + 1]);
                    }
                }
            }
        }

        // ---- Epilogue: d-frag rows (lane>>2, +8), cols (lane&3)*2 ----
#pragma unroll
        for (int mt = 0; mt < 2; mt++) {
#pragma unroll
            for (int n8 = 0; n8 < NW; n8++) {
                int col = wn * (NOUT / 2) + n8 * 8 + (lane & 3) * 2;
                float bx = bias[col], by = bias[col + 1];
                int r0w = row0 + wm * 32 + mt * 16 + (lane >> 2);
                float2 o0, o1;
                o0.x = acc[mt][n8][0] + bx;
                o0.y = acc[mt][n8][1] + by;
                o1.x = acc[mt][n8][2] + bx;
                o1.y = acc[mt][n8][3] + by;
                if (MODE <= 1) {
                    o0.x = fmaxf(o0.x, 0.f); o0.y = fmaxf(o0.y, 0.f);
                    o1.x = fmaxf(o1.x, 0.f); o1.y = fmaxf(o1.y, 0.f);
                }
                if (r0w < N)
                    *reinterpret_cast<float2*>(dstp + (size_t)r0w * NOUT + col) = o0;
                if (r0w + 8 < N)
                    *reinterpret_cast<float2*>(dstp + (size_t)(r0w + 8) * NOUT + col) = o1;
            }
        }
    }
}

// ============================ CSR build =====================================
__global__ void zero_deg_kernel(int nc) {
    int i = blockIdx.x * blockDim.x + threadIdx.x;
    int stride = gridDim.x * blockDim.x;
    for (; i < nc; i += stride) g_deg[i] = 0;
}
__global__ void hist_kernel(const int* __restrict__ ei, int E) {
    int i = blockIdx.x * blockDim.x + threadIdx.x;
    if (i < E) atomicAdd(&g_deg[ei[E + i]], 1);
}
__global__ void scan1_kernel(int nc) {
    __shared__ int s[256];
    int t = threadIdx.x;
    int i = blockIdx.x * 256 + t;
    s[t] = (i < nc) ? g_deg[i] : 0;
    __syncthreads();
    for (int d = 128; d > 0; d >>= 1) {
        if (t < d) s[t] += s[t + d];
        __syncthreads();
    }
    if (t == 0) g_bsum[blockIdx.x] = s[0];
}
__global__ void scan2_kernel(int nb) {
    __shared__ int s[512];
    int t = threadIdx.x;
    int v = (t < nb) ? g_bsum[t] : 0;
    s[t] = v;
    __syncthreads();
    for (int d = 1; d < 512; d <<= 1) {
        int add = (t >= d) ? s[t - d] : 0;
        __syncthreads();
        s[t] += add;
        __syncthreads();
    }
    if (t < nb) g_bsum[t] = s[t] - v;
}
__global__ void scan3_kernel(int nc) {
    __shared__ int s[256];
    int t = threadIdx.x;
    int i = blockIdx.x * 256 + t;
    int v = (i < nc) ? g_deg[i] : 0;
    s[t] = v;
    __syncthreads();
    for (int d = 1; d < 256; d <<= 1) {
        int add = (t >= d) ? s[t - d] : 0;
        __syncthreads();
        s[t] += add;
        __syncthreads();
    }
    if (i < nc) {
        int off = g_bsum[blockIdx.x] + s[t] - v;
        g_off[i] = off;
        g_cursor[i] = off;
    }
}
__global__ void fill_kernel(const int* __restrict__ ei, int E) {
    int i = blockIdx.x * blockDim.x + threadIdx.x;
    if (i < E) {
        int dst = ei[E + i];
        int pos = atomicAdd(&g_cursor[dst], 1);
        g_csr[pos] = ei[i];
    }
}

// ------------------- Gather-mean: warp per content node --------------------
__global__ void agg_kernel(int nc) {
    const int warp = (blockIdx.x * blockDim.x + threadIdx.x) >> 5;
    const int lane = threadIdx.x & 31;
    if (warp >= nc) return;
    const int s0 = g_off[warp];
    const int d = g_deg[warp];
    float4 acc = make_float4(0.f, 0.f, 0.f, 0.f);
    for (int base = 0; base < d; base += 32) {
        int my = (base + lane < d) ? g_csr[s0 + base + lane] : 0;
        int lim = min(32, d - base);
        for (int j = 0; j < lim; j++) {
            int nbr = __shfl_sync(0xffffffffu, my, j);
            float4 v = reinterpret_cast<const float4*>(g_hu + (size_t)nbr * H)[lane];
            acc.x += v.x; acc.y += v.y; acc.z += v.z; acc.w += v.w;
        }
    }
    float inv = 1.f / fmaxf((float)d, 1.f);
    acc.x *= inv; acc.y *= inv; acc.z *= inv; acc.w *= inv;
    reinterpret_cast<float4*>(g_mean + (size_t)warp * H)[lane] = acc;
}

// ---------------------------------------------------------------------------
extern "C" void kernel_launch(void* const* d_in, const int* in_sizes, int n_in,
                              void* d_out, int out_size) {
    const float* x_content = (const float*)d_in[0];
    const float* x_user    = (const float*)d_in[1];
    const int*   ei        = (const int*)d_in[2];   // int32 (JAX x64 off)
    const float* Wc = (const float*)d_in[3];
    const float* bc = (const float*)d_in[4];
    const float* Wu = (const float*)d_in[5];
    const float* bu = (const float*)d_in[6];
    const float* Wl = (const float*)d_in[7];
    const float* bl = (const float*)d_in[8];
    const float* Wr = (const float*)d_in[9];
    const float* Wo = (const float*)d_in[10];
    const float* bo = (const float*)d_in[11];
    float* out = (float*)d_out;

    const int Nc = in_sizes[0] / 256;
    const int Nu = in_sizes[1] / 128;
    const int E  = in_sizes[2] / 2;

    // smem = 2*128*136*2 (A hi/lo) + 2*KTOT*BPITCH*2 (B hi/lo)
    const int smem_m0 = 2 * 128 * 136 * 2 + 2 * 128 * 136 * 2;  // 139264
    const int smem_m1 = 2 * 128 * 136 * 2 + 2 * 256 * 136 * 2;  // 208896
    const int smem_m3 = 2 * 128 * 136 * 2 + 2 * 128 * 72 * 2;   // 106496

    cudaFuncSetAttribute(gemm_kernel<128, 128, 0>,
                         cudaFuncAttributeMaxDynamicSharedMemorySize, smem_m0);
    cudaFuncSetAttribute(gemm_kernel<256, 128, 1>,
                         cudaFuncAttributeMaxDynamicSharedMemorySize, smem_m1);
    cudaFuncSetAttribute(gemm_kernel<256, 128, 2>,
                         cudaFuncAttributeMaxDynamicSharedMemorySize, smem_m1);
    cudaFuncSetAttribute(gemm_kernel<128, 64, 3>,
                         cudaFuncAttributeMaxDynamicSharedMemorySize, smem_m3);

    // CSR build
    zero_deg_kernel<<<256, 256>>>(Nc);
    hist_kernel<<<(E + 255) / 256, 256>>>(ei, E);
    const int nb = (Nc + 255) / 256;  // <= 512
    scan1_kernel<<<nb, 256>>>(Nc);
    scan2_kernel<<<1, 512>>>(nb);
    scan3_kernel<<<nb, 256>>>(Nc);
    fill_kernel<<<(E + 255) / 256, 256>>>(ei, E);

    // Projections (HMMA bf16-split)
    gemm_kernel<128, 128, 0><<<152, 256, smem_m0>>>(x_user, Wu, nullptr, bu,
                                                    nullptr, Nu);
    gemm_kernel<256, 128, 1><<<152, 256, smem_m1>>>(x_content, Wc, nullptr, bc,
                                                    nullptr, Nc);

    // Gather-mean
    agg_kernel<<<(Nc * 32 + 255) / 256, 256>>>(Nc);

    // Combine: h = [mean|hc] @ [Wl;Wr] + bl
    gemm_kernel<256, 128, 2><<<152, 256, smem_m1>>>(nullptr, Wl, Wr, bl,
                                                    nullptr, Nc);
    // Output: out = h @ Wo + bo
    gemm_kernel<128, 64, 3><<<152, 256, smem_m3>>>(nullptr, Wo, nullptr, bo,
                                                   out, Nc);
}

// round 7
// speedup vs baseline: 1.9514x; 1.2076x over previous
#include <cuda_runtime.h>
#include <cuda_bf16.h>
#include <stdint.h>

#define H      128
#define NC_MAX 100000
#define NU_MAX 100000
#define E_MAX  1600000

// Scratch: __device__ globals (allocation-free rule)
__device__ __align__(16) float g_hu[(size_t)NU_MAX * H];
__device__ __align__(16) float g_hc[(size_t)NC_MAX * H];
__device__ __align__(16) float g_mean[(size_t)NC_MAX * H];
__device__ int g_deg[NC_MAX];
__device__ int g_off[NC_MAX];
__device__ int g_cursor[NC_MAX];
__device__ int g_csr[E_MAX];
__device__ int g_bsum[512];

// ============================= PTX helpers (portable) =======================
__device__ __forceinline__ uint32_t smem_u32(const void* p) {
    uint32_t a;
    asm("{ .reg .u64 t; cvta.to.shared.u64 t, %1; cvt.u32.u64 %0, t; }"
        : "=r"(a) : "l"(p));
    return a;
}
__device__ __forceinline__ void ldsm_x4(uint32_t* r, uint32_t addr) {
    asm volatile("ldmatrix.sync.aligned.m8n8.x4.shared.b16 {%0,%1,%2,%3}, [%4];"
                 : "=r"(r[0]), "=r"(r[1]), "=r"(r[2]), "=r"(r[3]) : "r"(addr));
}
__device__ __forceinline__ void ldsm_x4_t(uint32_t* r, uint32_t addr) {
    asm volatile("ldmatrix.sync.aligned.m8n8.x4.trans.shared.b16 {%0,%1,%2,%3}, [%4];"
                 : "=r"(r[0]), "=r"(r[1]), "=r"(r[2]), "=r"(r[3]) : "r"(addr));
}
__device__ __forceinline__ void mma_bf16(float* d, const uint32_t* a,
                                         uint32_t b0, uint32_t b1) {
    asm volatile(
        "mma.sync.aligned.m16n8k16.row.col.f32.bf16.bf16.f32 "
        "{%0,%1,%2,%3}, {%4,%5,%6,%7}, {%8,%9}, {%0,%1,%2,%3};"
        : "+f"(d[0]), "+f"(d[1]), "+f"(d[2]), "+f"(d[3])
        : "r"(a[0]), "r"(a[1]), "r"(a[2]), "r"(a[3]), "r"(b0), "r"(b1));
}

// fp32 -> (bf16 hi, bf16 lo), 4 values packed
__device__ __forceinline__ void cvt_hl4(float4 v, uint2& hv, uint2& lv) {
    float f[4] = {v.x, v.y, v.z, v.w};
    uint32_t h[4], l[4];
#pragma unroll
    for (int j = 0; j < 4; j++) {
        __nv_bfloat16 hb = __float2bfloat16_rn(f[j]);
        float hf = __bfloat162float(hb);
        __nv_bfloat16 lb = __float2bfloat16_rn(f[j] - hf);
        h[j] = (uint32_t)__bfloat16_as_ushort(hb);
        l[j] = (uint32_t)__bfloat16_as_ushort(lb);
    }
    hv = make_uint2(h[0] | (h[1] << 16), h[2] | (h[3] << 16));
    lv = make_uint2(l[0] | (l[1] << 16), l[2] | (l[3] << 16));
}
__device__ __forceinline__ void cvt_hl2(float a, float b, uint32_t& hv, uint32_t& lv) {
    __nv_bfloat16 h0 = __float2bfloat16_rn(a), h1 = __float2bfloat16_rn(b);
    float f0 = __bfloat162float(h0), f1 = __bfloat162float(h1);
    __nv_bfloat16 l0 = __float2bfloat16_rn(a - f0), l1 = __float2bfloat16_rn(b - f1);
    hv = (uint32_t)__bfloat16_as_ushort(h0) |
         ((uint32_t)__bfloat16_as_ushort(h1) << 16);
    lv = (uint32_t)__bfloat16_as_ushort(l0) |
         ((uint32_t)__bfloat16_as_ushort(l1) << 16);
}

// ============================================================================
// Projection GEMM core (NOUT=128): relu(X @ W + b) -> dst. 64-row tiles.
// MODE 0: X stride 128 (user). MODE 1: X stride 256, 2 chunks (content).
// 8 warps: wm=wid>>1 (16-row slice), wn=wid&1 (64-col half).
// ============================================================================
template <int KTOT, int MODE>
__device__ void run_proj(const float* __restrict__ X, const float* __restrict__ W,
                         const float* __restrict__ bias, float* __restrict__ dst,
                         int N, int bid, int nb, char* smc) {
    constexpr int NCHUNK = KTOT / 128;
    constexpr int PITCH = 136;
    __nv_bfloat16* Bh = reinterpret_cast<__nv_bfloat16*>(smc);
    __nv_bfloat16* Bl = Bh + KTOT * PITCH;
    __nv_bfloat16* Ah = Bl + KTOT * PITCH;
    __nv_bfloat16* Al = Ah + 64 * PITCH;

    const int t = threadIdx.x;
    const int wid = t >> 5, lane = t & 31;
    const int wm = wid >> 1, wn = wid & 1;

    // Stage weights hi/lo
    for (int i = t; i < KTOT * 32; i += 256) {
        int k = i >> 5, n4 = (i & 31) * 4;
        float4 w = *reinterpret_cast<const float4*>(W + (size_t)k * 128 + n4);
        uint2 hv, lv;
        cvt_hl4(w, hv, lv);
        *reinterpret_cast<uint2*>(Bh + k * PITCH + n4) = hv;
        *reinterpret_cast<uint2*>(Bl + k * PITCH + n4) = lv;
    }

    const uint32_t ah_u = smem_u32(Ah), al_u = smem_u32(Al);
    const uint32_t bh_u = smem_u32(Bh), bl_u = smem_u32(Bl);
    const int a_row_l = lane & 15, a_col_l = (lane >> 4) * 8;
    const int b_k_l = (lane & 7) + ((lane >> 3) & 1) * 8;
    const int b_n_l = (lane >> 4) * 8;

    float2 bv[8];
#pragma unroll
    for (int n8 = 0; n8 < 8; n8++)
        bv[n8] = *reinterpret_cast<const float2*>(bias + wn * 64 + n8 * 8 +
                                                  (lane & 3) * 2);

    const int ntiles = (N + 63) >> 6;
    for (int tile = bid; tile < ntiles; tile += nb) {
        const int row0 = tile << 6;
        float acc[8][4];
#pragma unroll
        for (int n8 = 0; n8 < 8; n8++)
#pragma unroll
            for (int e = 0; e < 4; e++) acc[n8][e] = 0.f;

        for (int c = 0; c < NCHUNK; ++c) {
            __syncthreads();
            // Batched load (8 LDG.128 in flight), then cvt+store
            float4 vv[8];
#pragma unroll
            for (int it = 0; it < 8; it++) {
                int i = t + it * 256;
                int rr = row0 + (i >> 5);
                int c4 = (i & 31) * 4;
                vv[it] = (rr < N)
                             ? *reinterpret_cast<const float4*>(
                                   X + (size_t)rr * KTOT + c * 128 + c4)
                             : make_float4(0.f, 0.f, 0.f, 0.f);
            }
#pragma unroll
            for (int it = 0; it < 8; it++) {
                int i = t + it * 256;
                int r = i >> 5, c4 = (i & 31) * 4;
                uint2 hv, lv;
                cvt_hl4(vv[it], hv, lv);
                *reinterpret_cast<uint2*>(Ah + r * PITCH + c4) = hv;
                *reinterpret_cast<uint2*>(Al + r * PITCH + c4) = lv;
            }
            __syncthreads();

#pragma unroll 1
            for (int k0 = 0; k0 < 128; k0 += 16) {
                uint32_t afh[4], afl[4];
                uint32_t aoff = (uint32_t)((wm * 16 + a_row_l) * PITCH + k0 + a_col_l) * 2;
                ldsm_x4(afh, ah_u + aoff);
                ldsm_x4(afl, al_u + aoff);
                uint32_t bfh[4][4], bfl[4][4];
#pragma unroll
                for (int ng = 0; ng < 4; ng++) {
                    uint32_t boff = (uint32_t)((c * 128 + k0 + b_k_l) * PITCH +
                                               wn * 64 + ng * 16 + b_n_l) * 2;
                    ldsm_x4_t(bfh[ng], bh_u + boff);
                    ldsm_x4_t(bfl[ng], bl_u + boff);
                }
#pragma unroll
                for (int n8 = 0; n8 < 8; n8++) {
                    int ng = n8 >> 1, sb = (n8 & 1) * 2;
                    mma_bf16(acc[n8], afh, bfh[ng][sb], bfh[ng][sb + 1]);
                    mma_bf16(acc[n8], afh, bfl[ng][sb], bfl[ng][sb + 1]);
                    mma_bf16(acc[n8], afl, bfh[ng][sb], bfh[ng][sb + 1]);
                }
            }
        }
        // Epilogue: relu(acc + b)
        int r0w = row0 + wm * 16 + (lane >> 2);
#pragma unroll
        for (int n8 = 0; n8 < 8; n8++) {
            int col = wn * 64 + n8 * 8 + (lane & 3) * 2;
            float2 o0, o1;
            o0.x = fmaxf(acc[n8][0] + bv[n8].x, 0.f);
            o0.y = fmaxf(acc[n8][1] + bv[n8].y, 0.f);
            o1.x = fmaxf(acc[n8][2] + bv[n8].x, 0.f);
            o1.y = fmaxf(acc[n8][3] + bv[n8].y, 0.f);
            if (r0w < N)
                *reinterpret_cast<float2*>(dst + (size_t)r0w * 128 + col) = o0;
            if (r0w + 8 < N)
                *reinterpret_cast<float2*>(dst + (size_t)(r0w + 8) * 128 + col) = o1;
        }
    }
}

// Fused projections: blocks 0-50 -> user (K=128), 51-151 -> content (K=256)
__global__ void __launch_bounds__(256, 1)
proj_fused(const float* __restrict__ xc, const float* __restrict__ xu,
           const float* __restrict__ Wc, const float* __restrict__ bc,
           const float* __restrict__ Wu, const float* __restrict__ bu,
           int Nc, int Nu) {
    extern __shared__ char smc[];
    if (blockIdx.x < 51)
        run_proj<128, 0>(xu, Wu, bu, g_hu, Nu, blockIdx.x, 51, smc);
    else
        run_proj<256, 1>(xc, Wc, bc, g_hc, Nc, blockIdx.x - 51, 101, smc);
}

// ============================================================================
// Combine + output fused: h = mean@Wl + bl + hc@Wr; out = h@Wo + bo.
// GEMM1 (K=256, N=128) in regs -> h to smem bf16 hi/lo -> GEMM2 (K=128, N=64).
// ============================================================================
__global__ void __launch_bounds__(256, 1)
combine_kernel(const float* __restrict__ Wl, const float* __restrict__ bl,
               const float* __restrict__ Wr, const float* __restrict__ Wo,
               const float* __restrict__ bo, float* __restrict__ out, int N) {
    constexpr int PITCH = 136, OPITCH = 72;
    extern __shared__ char smc[];
    __nv_bfloat16* Bh = reinterpret_cast<__nv_bfloat16*>(smc);
    __nv_bfloat16* Bl_ = Bh + 256 * PITCH;
    __nv_bfloat16* Ah = Bl_ + 256 * PITCH;
    __nv_bfloat16* Al = Ah + 64 * PITCH;
    __nv_bfloat16* Oh = Al + 64 * PITCH;
    __nv_bfloat16* Ol = Oh + 128 * OPITCH;

    const int t = threadIdx.x;
    const int wid = t >> 5, lane = t & 31;
    const int wm = wid >> 1, wn = wid & 1;

    // Stage [Wl;Wr] hi/lo
    for (int i = t; i < 256 * 32; i += 256) {
        int k = i >> 5, n4 = (i & 31) * 4;
        const float* wsrc = (k < 128) ? Wl + (size_t)k * 128
                                      : Wr + (size_t)(k - 128) * 128;
        float4 w = *reinterpret_cast<const float4*>(wsrc + n4);
        uint2 hv, lv;
        cvt_hl4(w, hv, lv);
        *reinterpret_cast<uint2*>(Bh + k * PITCH + n4) = hv;
        *reinterpret_cast<uint2*>(Bl_ + k * PITCH + n4) = lv;
    }
    // Stage Wo hi/lo
    for (int i = t; i < 128 * 16; i += 256) {
        int k = i >> 4, n4 = (i & 15) * 4;
        float4 w = *reinterpret_cast<const float4*>(Wo + (size_t)k * 64 + n4);
        uint2 hv, lv;
        cvt_hl4(w, hv, lv);
        *reinterpret_cast<uint2*>(Oh + k * OPITCH + n4) = hv;
        *reinterpret_cast<uint2*>(Ol + k * OPITCH + n4) = lv;
    }

    const uint32_t ah_u = smem_u32(Ah), al_u = smem_u32(Al);
    const uint32_t bh_u = smem_u32(Bh), bl_u = smem_u32(Bl_);
    const uint32_t oh_u = smem_u32(Oh), ol_u = smem_u32(Ol);
    const int a_row_l = lane & 15, a_col_l = (lane >> 4) * 8;
    const int b_k_l = (lane & 7) + ((lane >> 3) & 1) * 8;
    const int b_n_l = (lane >> 4) * 8;

    float2 blv[8];
#pragma unroll
    for (int n8 = 0; n8 < 8; n8++)
        blv[n8] = *reinterpret_cast<const float2*>(bl + wn * 64 + n8 * 8 +
                                                   (lane & 3) * 2);
    float2 bov[4];
#pragma unroll
    for (int n8 = 0; n8 < 4; n8++)
        bov[n8] = *reinterpret_cast<const float2*>(bo + wn * 32 + n8 * 8 +
                                                   (lane & 3) * 2);

    const int ntiles = (N + 63) >> 6;
    for (int tile = blockIdx.x; tile < ntiles; tile += gridDim.x) {
        const int row0 = tile << 6;
        float acc[8][4];
#pragma unroll
        for (int n8 = 0; n8 < 8; n8++)
#pragma unroll
            for (int e = 0; e < 4; e++) acc[n8][e] = 0.f;

        // ---- GEMM1: K=256 over [mean | hc] ----
        for (int c = 0; c < 2; ++c) {
            __syncthreads();
            const float* src = (c == 0) ? g_mean : g_hc;
            float4 vv[8];
#pragma unroll
            for (int it = 0; it < 8; it++) {
                int i = t + it * 256;
                int rr = row0 + (i >> 5);
                int c4 = (i & 31) * 4;
                vv[it] = (rr < N) ? *reinterpret_cast<const float4*>(
                                        src + (size_t)rr * 128 + c4)
                                  : make_float4(0.f, 0.f, 0.f, 0.f);
            }
#pragma unroll
            for (int it = 0; it < 8; it++) {
                int i = t + it * 256;
                int r = i >> 5, c4 = (i & 31) * 4;
                uint2 hv, lv;
                cvt_hl4(vv[it], hv, lv);
                *reinterpret_cast<uint2*>(Ah + r * PITCH + c4) = hv;
                *reinterpret_cast<uint2*>(Al + r * PITCH + c4) = lv;
            }
            __syncthreads();
#pragma unroll 1
            for (int k0 = 0; k0 < 128; k0 += 16) {
                uint32_t afh[4], afl[4];
                uint32_t aoff = (uint32_t)((wm * 16 + a_row_l) * PITCH + k0 + a_col_l) * 2;
                ldsm_x4(afh, ah_u + aoff);
                ldsm_x4(afl, al_u + aoff);
                uint32_t bfh[4][4], bfl[4][4];
#pragma unroll
                for (int ng = 0; ng < 4; ng++) {
                    uint32_t boff = (uint32_t)((c * 128 + k0 + b_k_l) * PITCH +
                                               wn * 64 + ng * 16 + b_n_l) * 2;
                    ldsm_x4_t(bfh[ng], bh_u + boff);
                    ldsm_x4_t(bfl[ng], bl_u + boff);
                }
#pragma unroll
                for (int n8 = 0; n8 < 8; n8++) {
                    int ng = n8 >> 1, sb = (n8 & 1) * 2;
                    mma_bf16(acc[n8], afh, bfh[ng][sb], bfh[ng][sb + 1]);
                    mma_bf16(acc[n8], afh, bfl[ng][sb], bfl[ng][sb + 1]);
                    mma_bf16(acc[n8], afl, bfh[ng][sb], bfh[ng][sb + 1]);
                }
            }
        }
        __syncthreads();  // GEMM1 smem reads done; reuse Ah/Al for h

        // ---- h = acc + bl -> smem (bf16 hi/lo) ----
        {
            int r1 = wm * 16 + (lane >> 2);
#pragma unroll
            for (int n8 = 0; n8 < 8; n8++) {
                int col = wn * 64 + n8 * 8 + (lane & 3) * 2;
                uint32_t hv, lv;
                cvt_hl2(acc[n8][0] + blv[n8].x, acc[n8][1] + blv[n8].y, hv, lv);
                *reinterpret_cast<uint32_t*>(Ah + r1 * PITCH + col) = hv;
                *reinterpret_cast<uint32_t*>(Al + r1 * PITCH + col) = lv;
                cvt_hl2(acc[n8][2] + blv[n8].x, acc[n8][3] + blv[n8].y, hv, lv);
                *reinterpret_cast<uint32_t*>(Ah + (r1 + 8) * PITCH + col) = hv;
                *reinterpret_cast<uint32_t*>(Al + (r1 + 8) * PITCH + col) = lv;
            }
        }
        __syncthreads();

        // ---- GEMM2: out = h @ Wo + bo (K=128, N=64) ----
        float acc2[4][4];
#pragma unroll
        for (int n8 = 0; n8 < 4; n8++)
#pragma unroll
            for (int e = 0; e < 4; e++) acc2[n8][e] = 0.f;
#pragma unroll 1
        for (int k0 = 0; k0 < 128; k0 += 16) {
            uint32_t afh[4], afl[4];
            uint32_t aoff = (uint32_t)((wm * 16 + a_row_l) * PITCH + k0 + a_col_l) * 2;
            ldsm_x4(afh, ah_u + aoff);
            ldsm_x4(afl, al_u + aoff);
            uint32_t bfh[2][4], bfl[2][4];
#pragma unroll
            for (int ng = 0; ng < 2; ng++) {
                uint32_t boff = (uint32_t)((k0 + b_k_l) * OPITCH +
                                           wn * 32 + ng * 16 + b_n_l) * 2;
                ldsm_x4_t(bfh[ng], oh_u + boff);
                ldsm_x4_t(bfl[ng], ol_u + boff);
            }
#pragma unroll
            for (int n8 = 0; n8 < 4; n8++) {
                int ng = n8 >> 1, sb = (n8 & 1) * 2;
                mma_bf16(acc2[n8], afh, bfh[ng][sb], bfh[ng][sb + 1]);
                mma_bf16(acc2[n8], afh, bfl[ng][sb], bfl[ng][sb + 1]);
                mma_bf16(acc2[n8], afl, bfh[ng][sb], bfh[ng][sb + 1]);
            }
        }
        // Epilogue 2
        int r0w = row0 + wm * 16 + (lane >> 2);
#pragma unroll
        for (int n8 = 0; n8 < 4; n8++) {
            int col = wn * 32 + n8 * 8 + (lane & 3) * 2;
            float2 o0, o1;
            o0.x = acc2[n8][0] + bov[n8].x;
            o0.y = acc2[n8][1] + bov[n8].y;
            o1.x = acc2[n8][2] + bov[n8].x;
            o1.y = acc2[n8][3] + bov[n8].y;
            if (r0w < N)
                *reinterpret_cast<float2*>(out + (size_t)r0w * 64 + col) = o0;
            if (r0w + 8 < N)
                *reinterpret_cast<float2*>(out + (size_t)(r0w + 8) * 64 + col) = o1;
        }
    }
}

// ============================ CSR build =====================================
__global__ void zero_deg_kernel(int nc) {
    int i = blockIdx.x * blockDim.x + threadIdx.x;
    int stride = gridDim.x * blockDim.x;
    for (; i < nc; i += stride) g_deg[i] = 0;
}
__global__ void hist_kernel(const int* __restrict__ ei, int E) {
    int i = blockIdx.x * blockDim.x + threadIdx.x;
    if (i < E) atomicAdd(&g_deg[ei[E + i]], 1);
}
__global__ void scan1_kernel(int nc) {
    __shared__ int s[256];
    int t = threadIdx.x;
    int i = blockIdx.x * 256 + t;
    s[t] = (i < nc) ? g_deg[i] : 0;
    __syncthreads();
    for (int d = 128; d > 0; d >>= 1) {
        if (t < d) s[t] += s[t + d];
        __syncthreads();
    }
    if (t == 0) g_bsum[blockIdx.x] = s[0];
}
__global__ void scan2_kernel(int nb) {
    __shared__ int s[512];
    int t = threadIdx.x;
    int v = (t < nb) ? g_bsum[t] : 0;
    s[t] = v;
    __syncthreads();
    for (int d = 1; d < 512; d <<= 1) {
        int add = (t >= d) ? s[t - d] : 0;
        __syncthreads();
        s[t] += add;
        __syncthreads();
    }
    if (t < nb) g_bsum[t] = s[t] - v;
}
__global__ void scan3_kernel(int nc) {
    __shared__ int s[256];
    int t = threadIdx.x;
    int i = blockIdx.x * 256 + t;
    int v = (i < nc) ? g_deg[i] : 0;
    s[t] = v;
    __syncthreads();
    for (int d = 1; d < 256; d <<= 1) {
        int add = (t >= d) ? s[t - d] : 0;
        __syncthreads();
        s[t] += add;
        __syncthreads();
    }
    if (i < nc) {
        int off = g_bsum[blockIdx.x] + s[t] - v;
        g_off[i] = off;
        g_cursor[i] = off;
    }
}
__global__ void fill_kernel(const int* __restrict__ ei, int E) {
    int i = blockIdx.x * blockDim.x + threadIdx.x;
    if (i < E) {
        int dst = ei[E + i];
        int pos = atomicAdd(&g_cursor[dst], 1);
        g_csr[pos] = ei[i];
    }
}

// ------------------- Gather-mean: warp per content node --------------------
__global__ void agg_kernel(int nc) {
    const int warp = (blockIdx.x * blockDim.x + threadIdx.x) >> 5;
    const int lane = threadIdx.x & 31;
    if (warp >= nc) return;
    const int s0 = g_off[warp];
    const int d = g_deg[warp];
    float4 acc = make_float4(0.f, 0.f, 0.f, 0.f);
    for (int base = 0; base < d; base += 32) {
        int my = (base + lane < d) ? g_csr[s0 + base + lane] : 0;
        int lim = min(32, d - base);
        for (int j = 0; j < lim; j++) {
            int nbr = __shfl_sync(0xffffffffu, my, j);
            float4 v = reinterpret_cast<const float4*>(g_hu + (size_t)nbr * H)[lane];
            acc.x += v.x; acc.y += v.y; acc.z += v.z; acc.w += v.w;
        }
    }
    float inv = 1.f / fmaxf((float)d, 1.f);
    acc.x *= inv; acc.y *= inv; acc.z *= inv; acc.w *= inv;
    reinterpret_cast<float4*>(g_mean + (size_t)warp * H)[lane] = acc;
}

// ---------------------------------------------------------------------------
extern "C" void kernel_launch(void* const* d_in, const int* in_sizes, int n_in,
                              void* d_out, int out_size) {
    const float* x_content = (const float*)d_in[0];
    const float* x_user    = (const float*)d_in[1];
    const int*   ei        = (const int*)d_in[2];   // int32 (JAX x64 off)
    const float* Wc = (const float*)d_in[3];
    const float* bc = (const float*)d_in[4];
    const float* Wu = (const float*)d_in[5];
    const float* bu = (const float*)d_in[6];
    const float* Wl = (const float*)d_in[7];
    const float* bl = (const float*)d_in[8];
    const float* Wr = (const float*)d_in[9];
    const float* Wo = (const float*)d_in[10];
    const float* bo = (const float*)d_in[11];
    float* out = (float*)d_out;

    const int Nc = in_sizes[0] / 256;
    const int Nu = in_sizes[1] / 128;
    const int E  = in_sizes[2] / 2;

    // proj_fused: content path = (2*256*136 + 2*64*136)*2 = 174080 B
    const int smem_proj = (2 * 256 * 136 + 2 * 64 * 136) * 2;
    // combine: (2*256*136 + 2*64*136 + 2*128*72)*2 = 210944 B
    const int smem_comb = (2 * 256 * 136 + 2 * 64 * 136 + 2 * 128 * 72) * 2;

    cudaFuncSetAttribute(proj_fused,
                         cudaFuncAttributeMaxDynamicSharedMemorySize, smem_proj);
    cudaFuncSetAttribute(combine_kernel,
                         cudaFuncAttributeMaxDynamicSharedMemorySize, smem_comb);

    const int nb = (Nc + 255) / 256;  // <= 512

    zero_deg_kernel<<<256, 256>>>(Nc);
    hist_kernel<<<(E + 255) / 256, 256>>>(ei, E);
    scan1_kernel<<<nb, 256>>>(Nc);
    proj_fused<<<152, 256, smem_proj>>>(x_content, x_user, Wc, bc, Wu, bu, Nc, Nu);
    scan2_kernel<<<1, 512>>>(nb);
    scan3_kernel<<<nb, 256>>>(Nc);
    fill_kernel<<<(E + 255) / 256, 256>>>(ei, E);
    agg_kernel<<<(Nc * 32 + 255) / 256, 256>>>(Nc);
    combine_kernel<<<152, 256, smem_comb>>>(Wl, bl, Wr, Wo, bo, out, Nc);
}